// round 7
// baseline (speedup 1.0000x reference)
#include <cuda_runtime.h>
#include <cuda_fp16.h>
#include <cstdint>

// LoRAConv3d: out = conv3(x,W) + bias + 2*B@boxsum3(conv3(x,A))
// Pipeline: pad_x, prep_w, low_conv (N=16) -> g_low, boxsum -> g_ls,
//           conv (N=128) with fused lora epilogue.
// Implicit GEMM on mma.sync.m16n8k16 (f16 in, f32 acc).

__device__ __half  xpad[2 * 34 * 34 * 34 * 64];   // padded NDHWC fp16
__device__ __half  wk[27 * 144 * 64];             // [off][n][c], n<128 base, n>=128 rank
__device__ float   g_low[2 * 16 * 32768];
__device__ float   g_ls[2 * 16 * 32768];

// ---------------- helpers ----------------
__device__ __forceinline__ uint32_t smem_u32(const void* p) {
    uint32_t a;
    asm("{ .reg .u64 t; cvta.to.shared.u64 t, %1; cvt.u32.u64 %0, t; }" : "=r"(a) : "l"(p));
    return a;
}
__device__ __forceinline__ void cp16(uint32_t dst, const void* src) {
    asm volatile("cp.async.cg.shared.global [%0], [%1], 16;" :: "r"(dst), "l"(src));
}
__device__ __forceinline__ void cp_commit() { asm volatile("cp.async.commit_group;"); }
template <int N> __device__ __forceinline__ void cp_wait() {
    asm volatile("cp.async.wait_group %0;" :: "n"(N) : "memory");
}
__device__ __forceinline__ void ldsm4(uint32_t* r, uint32_t addr) {
    asm volatile("ldmatrix.sync.aligned.m8n8.x4.shared.b16 {%0,%1,%2,%3}, [%4];"
                 : "=r"(r[0]), "=r"(r[1]), "=r"(r[2]), "=r"(r[3]) : "r"(addr));
}
__device__ __forceinline__ void mma16816(float* c, const uint32_t* a,
                                         uint32_t b0, uint32_t b1) {
    asm volatile(
        "mma.sync.aligned.m16n8k16.row.col.f32.f16.f16.f32 "
        "{%0,%1,%2,%3}, {%4,%5,%6,%7}, {%8,%9}, {%0,%1,%2,%3};"
        : "+f"(c[0]), "+f"(c[1]), "+f"(c[2]), "+f"(c[3])
        : "r"(a[0]), "r"(a[1]), "r"(a[2]), "r"(a[3]), "r"(b0), "r"(b1));
}

// ---------------- prep kernels ----------------
__global__ __launch_bounds__(256) void pad_x_kernel(const float* __restrict__ x) {
    int id = blockIdx.x;                       // 2*34*34
    int b = id / 1156, rem = id - b * 1156;
    int zp = rem / 34, yp = rem - zp * 34;
    const bool interior = (zp >= 1 && zp <= 32 && yp >= 1 && yp <= 32);
    __shared__ float s[2048];                  // [c][x]
    if (interior) {
        for (int i = threadIdx.x; i < 2048; i += 256) {
            int c = i >> 5, xx = i & 31;
            s[i] = x[((b * 64 + c) << 15) + ((zp - 1) << 10) + ((yp - 1) << 5) + xx];
        }
    }
    __syncthreads();
    __half* dst = xpad + (size_t)((b * 34 + zp) * 34 + yp) * 34 * 64;
    for (int i = threadIdx.x; i < 2176; i += 256) {
        int xi = i >> 6, c = i & 63;
        float v = (interior && xi >= 1 && xi <= 32) ? s[(c << 5) + (xi - 1)] : 0.f;
        dst[i] = __float2half(v);
    }
}

__global__ void prep_w_kernel(const float* __restrict__ weight,
                              const float* __restrict__ lora_A) {
    int i = blockIdx.x * 256 + threadIdx.x;    // 27*144*64
    if (i >= 27 * 144 * 64) return;
    int c = i & 63;
    int n = (i >> 6) % 144;
    int off = i / 9216;
    float v = (n < 128) ? weight[n * 1728 + c * 27 + off]
                        : lora_A[(n - 128) * 1728 + c * 27 + off];
    wk[i] = __float2half(v);
}

// ---------------- low conv: conv(x, lora_A), N=16 ----------------
// per CTA: M=256 (4z x 4y x 16x), N=16. halo 6z x 6y x 18x = 648 rows x 144B.
#define LSA_BYTES  (648 * 144)                 // 93312
#define LSB_STRIDE (16 * 144)                  // 2304
#define LSMEM_TOTAL (LSA_BYTES + 2 * LSB_STRIDE)   // 97920

__global__ __launch_bounds__(256, 2) void low_conv_kernel()
{
    extern __shared__ char smem[];
    const uint32_t sA = smem_u32(smem);
    const uint32_t sB = sA + LSA_BYTES;

    const int tid = threadIdx.x, lane = tid & 31, wid = tid >> 5;
    const int t = blockIdx.x;                  // 256 tiles
    const int b  = t >> 7;
    const int r  = t & 127;                    // 8 z x 8 y x 2 x
    const int z0 = (r >> 4) * 4;
    const int y0 = ((r >> 1) & 7) * 4;
    const int x0 = (r & 1) * 16;

    // stage A halo
    {
        const char* xb = (const char*)xpad;
        for (int i = tid; i < 5184; i += 256) {
            int rr = i >> 3, k = i & 7;
            int zz = rr / 108, rem = rr - zz * 108;
            int yy = rem / 18, xx = rem - yy * 18;
            size_t src = ((size_t)(((b * 34 + z0 + zz) * 34 + (y0 + yy)) * 34 + (x0 + xx)))
                         * 128 + k * 16;
            cp16(sA + rr * 144 + k * 16, xb + src);
        }
    }
    // stage B (rank rows 128..143 of wk)
    {
        const char* wb = (const char*)wk + 16384;
        for (int i = tid; i < 128; i += 256) {
            int row = i >> 3, k = i & 7;
            cp16(sB + row * 144 + k * 16, wb + row * 128 + k * 16);
        }
    }
    cp_commit();

    const int m0w = wid * 32;
    uint32_t laneA[2];
#pragma unroll
    for (int mi = 0; mi < 2; ++mi) {
        int m = m0w + mi * 16 + (lane & 15);
        int zi = m >> 6, yi = (m >> 4) & 3, xi = m & 15;
        laneA[mi] = (uint32_t)((zi * 108 + yi * 18 + xi) * 144 + ((lane >> 4) << 4));
    }
    const uint32_t laneB4 =
        (uint32_t)((((lane >> 4) & 1) * 8 + (lane & 7)) * 144 + ((lane >> 3) & 1) * 16);

    float acc[2][2][4];
#pragma unroll
    for (int mi = 0; mi < 2; ++mi)
#pragma unroll
        for (int nj = 0; nj < 2; ++nj)
#pragma unroll
            for (int q = 0; q < 4; ++q) acc[mi][nj][q] = 0.f;

    for (int off = 0; off < 27; ++off) {
        cp_wait<0>();
        __syncthreads();
        if (off < 26) {
            const char* wb = (const char*)wk + (size_t)(off + 1) * 18432 + 16384;
            uint32_t buf = sB + ((off + 1) & 1) * LSB_STRIDE;
            for (int i = tid; i < 128; i += 256) {
                int row = i >> 3, k = i & 7;
                cp16(buf + row * 144 + k * 16, wb + row * 128 + k * 16);
            }
            cp_commit();
        }
        const int dz = off / 9, r9 = off - dz * 9;
        const int dy = r9 / 3, dx = r9 - dy * 3;
        const uint32_t aoff = sA + (uint32_t)((dz * 108 + dy * 18 + dx) * 144);
        const uint32_t b4 = sB + (off & 1) * LSB_STRIDE + laneB4;

#pragma unroll
        for (int s = 0; s < 4; ++s) {
            const uint32_t so = (uint32_t)(s * 32);
            uint32_t a0[4], a1[4], bf[4];
            ldsm4(a0, aoff + laneA[0] + so);
            ldsm4(a1, aoff + laneA[1] + so);
            ldsm4(bf, b4 + so);
#pragma unroll
            for (int nj = 0; nj < 2; ++nj) {
                mma16816(acc[0][nj], a0, bf[nj * 2], bf[nj * 2 + 1]);
                mma16816(acc[1][nj], a1, bf[nj * 2], bf[nj * 2 + 1]);
            }
        }
    }

#pragma unroll
    for (int mi = 0; mi < 2; ++mi) {
        const int r0 = m0w + mi * 16 + (lane >> 2);
        const int r1 = r0 + 8;
        const int pos0 = (z0 + (r0 >> 6)) * 1024 + (y0 + ((r0 >> 4) & 3)) * 32
                         + x0 + (r0 & 15);
        const int pos1 = (z0 + (r1 >> 6)) * 1024 + (y0 + ((r1 >> 4) & 3)) * 32
                         + x0 + (r1 & 15);
#pragma unroll
        for (int nj = 0; nj < 2; ++nj) {
            const int c0 = nj * 8 + ((lane & 3) << 1);
#pragma unroll
            for (int q = 0; q < 4; ++q) {
                const int c = c0 + (q & 1);
                const int pos = (q < 2) ? pos0 : pos1;
                g_low[(size_t)(b * 16 + c) * 32768 + pos] = acc[mi][nj][q];
            }
        }
    }
}

// ---------------- boxsum: g_low -> g_ls ----------------
#define BOX_SMEM (16 * 1024 * 4)
__global__ __launch_bounds__(1024) void boxsum_kernel()
{
    extern __shared__ float zsum[];    // [16][32*32]
    const int id = blockIdx.x;         // 64: b*32+z
    const int z = id & 31, b = id >> 5;
    const int tid = threadIdx.x;
    const int y = tid >> 5, xx = tid & 31;

#pragma unroll
    for (int r = 0; r < 16; ++r) {
        const float* base = g_low + ((size_t)(b * 16 + r) << 15);
        float s = 0.f;
#pragma unroll
        for (int zz = -1; zz <= 1; ++zz) {
            int zin = z + zz;
            if ((unsigned)zin < 32u) s += base[(zin << 10) + tid];
        }
        zsum[(r << 10) + tid] = s;
    }
    __syncthreads();

#pragma unroll
    for (int r = 0; r < 16; ++r) {
        float a = 0.f;
#pragma unroll
        for (int dy = -1; dy <= 1; ++dy) {
            int yy = y + dy;
            if ((unsigned)yy < 32u) {
                const float* row = zsum + (r << 10) + (yy << 5);
#pragma unroll
                for (int dx = -1; dx <= 1; ++dx) {
                    int xn = xx + dx;
                    if ((unsigned)xn < 32u) a += row[xn];
                }
            }
        }
        g_ls[((size_t)(b * 16 + r) << 15) + (z << 10) + tid] = a;
    }
}

// ---------------- main conv: N=128 + fused lora epilogue ----------------
// per CTA: M=128 (2z x 4y x 16x), N=128. halo 4z x 6y x 18x = 432 rows x 144B.
#define SA_BYTES   (432 * 144)                 // 62208
#define SB_STRIDE  (128 * 144)                 // 18432
#define SB_OFF     SA_BYTES
#define SBIAS_OFF  (SA_BYTES + 2 * SB_STRIDE)  // 99072
#define SMEM_TOTAL (SBIAS_OFF + 512)           // 99584
// epilogue aliases (over sA region, after mainloop):
#define EP_BT_OFF  0                           // 16*128 floats = 8192 B
#define EP_LS_OFF  8192                        // 128*20 floats = 10240 B

__device__ __forceinline__ void stage_B128(uint32_t buf, int off, int tid) {
    const char* wb = (const char*)wk + (size_t)off * 18432;
#pragma unroll
    for (int i = tid; i < 1024; i += 256) {
        int row = i >> 3, k = i & 7;
        cp16(buf + row * 144 + k * 16, wb + row * 128 + k * 16);
    }
}

__global__ __launch_bounds__(256, 2) void conv_mma_kernel(
    const float* __restrict__ bias, const float* __restrict__ lora_B,
    float* __restrict__ out)
{
    extern __shared__ char smem[];
    const uint32_t sb = smem_u32(smem);
    const uint32_t sA = sb, sB = sb + SB_OFF;
    float* sbias = (float*)(smem + SBIAS_OFF);

    const int tid = threadIdx.x, lane = tid & 31, wid = tid >> 5;
    const int t = blockIdx.x;                  // 512 tiles
    const int b  = t >> 8;
    const int r  = t & 255;
    const int z0 = (r >> 4) * 2;
    const int y0 = ((r >> 1) & 7) * 4;
    const int x0 = (r & 1) * 16;

    if (tid < 128) sbias[tid] = bias[tid];

    // stage A halo
    {
        const char* xb = (const char*)xpad;
        for (int i = tid; i < 3456; i += 256) {
            int rr = i >> 3, k = i & 7;
            int dz = rr / 108, rem = rr - dz * 108;
            int yi = rem / 18, xi = rem - yi * 18;
            size_t src = ((size_t)(((b * 34 + z0 + dz) * 34 + (y0 + yi)) * 34 + (x0 + xi)))
                         * 128 + k * 16;
            cp16(sA + rr * 144 + k * 16, xb + src);
        }
    }
    stage_B128(sB, 0, tid);
    cp_commit();

    const int m0w = (wid >> 1) * 32;
    const int n0w = (wid & 1) * 64;
    uint32_t laneA[2];
#pragma unroll
    for (int mi = 0; mi < 2; ++mi) {
        int m = m0w + mi * 16 + (lane & 15);
        int zi = m >> 6, yi = (m >> 4) & 3, xi = m & 15;
        laneA[mi] = (uint32_t)((zi * 108 + yi * 18 + xi) * 144 + ((lane >> 4) << 4));
    }
    const uint32_t laneB4 =
        (uint32_t)((n0w + ((lane >> 4) & 1) * 8 + (lane & 7)) * 144
                   + ((lane >> 3) & 1) * 16);

    float acc[2][8][4];
#pragma unroll
    for (int mi = 0; mi < 2; ++mi)
#pragma unroll
        for (int nj = 0; nj < 8; ++nj)
#pragma unroll
            for (int q = 0; q < 4; ++q) acc[mi][nj][q] = 0.f;

    for (int off = 0; off < 27; ++off) {
        cp_wait<0>();
        __syncthreads();
        if (off < 26) {
            stage_B128(sB + ((off + 1) & 1) * SB_STRIDE, off + 1, tid);
            cp_commit();
        }
        const int dz = off / 9, r9 = off - dz * 9;
        const int dy = r9 / 3, dx = r9 - dy * 3;
        const uint32_t aoff = sA + (uint32_t)((dz * 108 + dy * 18 + dx) * 144);
        const uint32_t b4 = sB + (off & 1) * SB_STRIDE + laneB4;

#pragma unroll
        for (int s = 0; s < 4; ++s) {
            const uint32_t so = (uint32_t)(s * 32);
            uint32_t a0[4], a1[4];
            ldsm4(a0, aoff + laneA[0] + so);
            ldsm4(a1, aoff + laneA[1] + so);
            uint32_t bf[16];
#pragma unroll
            for (int p = 0; p < 4; ++p) ldsm4(&bf[p * 4], b4 + p * 2304 + so);
#pragma unroll
            for (int nj = 0; nj < 8; ++nj) {
                const uint32_t bv0 = bf[(nj >> 1) * 4 + (nj & 1) * 2];
                const uint32_t bv1 = bf[(nj >> 1) * 4 + (nj & 1) * 2 + 1];
                mma16816(acc[0][nj], a0, bv0, bv1);
                mma16816(acc[1][nj], a1, bv0, bv1);
            }
        }
    }

    // ---- fused lora epilogue ----
    __syncthreads();                           // mainloop smem dead; alias it
    float* sBt2 = (float*)(smem + EP_BT_OFF);  // [r][128], pre-scaled by 2
    float* ls_s = (float*)(smem + EP_LS_OFF);  // [pos][stride 20]

    for (int i = tid; i < 2048; i += 256) {
        int c = i >> 4, rr = i & 15;
        sBt2[rr * 128 + c] = 2.0f * lora_B[i];
    }
    for (int i = tid; i < 2048; i += 256) {
        int p = i & 127, rr = i >> 7;
        int posG = (z0 + (p >> 6)) * 1024 + (y0 + ((p >> 4) & 3)) * 32 + x0 + (p & 15);
        ls_s[p * 20 + rr] = g_ls[((size_t)(b * 16 + rr) << 15) + posG];
    }
    __syncthreads();

#pragma unroll
    for (int rr = 0; rr < 16; ++rr) {
        float bt[16];
#pragma unroll
        for (int j = 0; j < 16; ++j) {
            int c = n0w + (j >> 1) * 8 + ((lane & 3) << 1) + (j & 1);
            bt[j] = sBt2[rr * 128 + c];
        }
#pragma unroll
        for (int mi = 0; mi < 2; ++mi) {
#pragma unroll
            for (int q01 = 0; q01 < 2; ++q01) {
                const int rowm = m0w + mi * 16 + (lane >> 2) + q01 * 8;
                const float lsv = ls_s[rowm * 20 + rr];
#pragma unroll
                for (int nj = 0; nj < 8; ++nj) {
#pragma unroll
                    for (int cq = 0; cq < 2; ++cq)
                        acc[mi][nj][q01 * 2 + cq] =
                            fmaf(bt[nj * 2 + cq], lsv, acc[mi][nj][q01 * 2 + cq]);
                }
            }
        }
    }

    // store
#pragma unroll
    for (int mi = 0; mi < 2; ++mi) {
        const int r0 = m0w + mi * 16 + (lane >> 2);
        const int r1 = r0 + 8;
        const int pos0 = (z0 + (r0 >> 6)) * 1024 + (y0 + ((r0 >> 4) & 3)) * 32
                         + x0 + (r0 & 15);
        const int pos1 = (z0 + (r1 >> 6)) * 1024 + (y0 + ((r1 >> 4) & 3)) * 32
                         + x0 + (r1 & 15);
#pragma unroll
        for (int nj = 0; nj < 8; ++nj) {
            const int c0 = n0w + nj * 8 + ((lane & 3) << 1);
#pragma unroll
            for (int q = 0; q < 4; ++q) {
                const int c = c0 + (q & 1);
                const int pos = (q < 2) ? pos0 : pos1;
                out[(size_t)(b * 128 + c) * 32768 + pos] = acc[mi][nj][q] + sbias[c];
            }
        }
    }
}

// ---------------- launch ----------------
extern "C" void kernel_launch(void* const* d_in, const int* in_sizes, int n_in,
                              void* d_out, int out_size)
{
    const float* x      = (const float*)d_in[0];
    const float* weight = (const float*)d_in[1];
    const float* bias   = (const float*)d_in[2];
    const float* lora_A = (const float*)d_in[3];
    const float* lora_B = (const float*)d_in[4];
    float* out = (float*)d_out;

    cudaFuncSetAttribute(conv_mma_kernel,
                         cudaFuncAttributeMaxDynamicSharedMemorySize, SMEM_TOTAL);
    cudaFuncSetAttribute(low_conv_kernel,
                         cudaFuncAttributeMaxDynamicSharedMemorySize, LSMEM_TOTAL);
    cudaFuncSetAttribute(boxsum_kernel,
                         cudaFuncAttributeMaxDynamicSharedMemorySize, BOX_SMEM);

    pad_x_kernel<<<2312, 256>>>(x);
    prep_w_kernel<<<(27 * 144 * 64 + 255) / 256, 256>>>(weight, lora_A);
    low_conv_kernel<<<256, 256, LSMEM_TOTAL>>>();
    boxsum_kernel<<<64, 1024, BOX_SMEM>>>();
    conv_mma_kernel<<<512, 256, SMEM_TOTAL>>>(bias, lora_B, out);
}